// round 16
// baseline (speedup 1.0000x reference)
#include <cuda_runtime.h>
#include <cstddef>
#include <cstdint>

// Butterfly n=1024, log_n=10, increasing stride, + bias. 32768 rows.
//
// R15 = R14 topology (256 thr, 2 pairs/thread {k,k+256}; stages 8,9 thread-
// local; 3 smem exchange rounds, barriers scoped 64/128/256; deferred
// scaling; TMA bulk ring dist 2) with THREE rows per iteration:
//   - barriers/row: 1.0 (best so far); skeleton amortized over 3 rows
//   - 6 independent FMA/shfl chains per lockstep region
//   - exchange rows 0,1 packed as float2 (STS.64/LDS.64)
// launch_bounds(256,3), GRID=444.

constexpr int TPB  = 256;
constexpr int GRID = 444;

__device__ __forceinline__ void barx(int id, int cnt) {
    asm volatile("bar.sync %0, %1;" :: "r"(id), "r"(cnt) : "memory");
}
__device__ __forceinline__ void mbar_init(uint32_t a, uint32_t cnt) {
    asm volatile("mbarrier.init.shared.b64 [%0], %1;" :: "r"(a), "r"(cnt) : "memory");
}
__device__ __forceinline__ void mbar_expect_tx(uint32_t a, uint32_t bytes) {
    asm volatile("mbarrier.arrive.expect_tx.shared.b64 _, [%0], %1;" :: "r"(a), "r"(bytes) : "memory");
}
__device__ __forceinline__ void bulk_ld(uint32_t dst, const void* src, uint32_t bytes, uint32_t mbar) {
    asm volatile("cp.async.bulk.shared::cta.global.mbarrier::complete_tx::bytes [%0], [%1], %2, [%3];"
                 :: "r"(dst), "l"(src), "r"(bytes), "r"(mbar) : "memory");
}
__device__ __forceinline__ void mbar_wait(uint32_t a, uint32_t parity) {
    asm volatile(
        "{\n\t"
        ".reg .pred P;\n\t"
        "LW%=:\n\t"
        "mbarrier.try_wait.parity.acquire.cta.shared::cta.b64 P, [%0], %1, 0x989680;\n\t"
        "@P bra.uni LD%=;\n\t"
        "bra.uni LW%=;\n\t"
        "LD%=:\n\t"
        "}"
        :: "r"(a), "r"(parity) : "memory");
}

// pre-permuted twiddle for (pair p, stage i): validated steering
__device__ __forceinline__ float4 loadT(const float4* tw4, int p, int i) {
    float4 t = tw4[i * 512 + p];
    const bool rsw = (i <= 8) && (((p >> i) & 1) != 0);
    const bool csw = (i >= 1) && (((p >> (i - 1)) & 1) != 0);
    if (rsw) t = make_float4(t.z, t.w, t.x, t.y);
    if (csw) t = make_float4(t.y, t.x, t.w, t.z);
    return t;
}

__global__ __launch_bounds__(TPB, 3)
void butterfly_kernel(const float* __restrict__ x,
                      const float* __restrict__ tw,
                      const float* __restrict__ bias,
                      float* __restrict__ out,
                      int nrows)
{
    __shared__ __align__(16) float ring[3][3072];   // 36 KB: 3 slots x 3 rows
    __shared__ float2 ex2A[512], ex2B[512], ex2C[512];  // rows 0,1 packed (12 KB)
    __shared__ float  ex1A[512], ex1B[512], ex1C[512];  // row 2 (6 KB)
    __shared__ __align__(8) unsigned long long mbar[3];
    const int k = threadIdx.x;      // pair a = k, pair b = k + 256
    const int w = k >> 5;           // warp 0..7

    const uint32_t mb0 = (uint32_t)__cvta_generic_to_shared(&mbar[0]);
    const uint32_t rg0 = (uint32_t)__cvta_generic_to_shared(&ring[0][0]);

    if (k == 0) {
        mbar_init(mb0,      1);
        mbar_init(mb0 + 8,  1);
        mbar_init(mb0 + 16, 1);
    }

    // ---- deferred-scaling coefficients, both pairs -------------------------
    const float4* tw4 = reinterpret_cast<const float4*>(tw);
    float alpA[8], betA[8], alpB[8], betB[8];
    float cPa = 1.f, sQa = 1.f, cPb = 1.f, sQb = 1.f;
#pragma unroll
    for (int j = 0; j < 8; ++j) {
        const float4 t = loadT(tw4, k, j);
        alpA[j] = (t.y * sQa) / (t.x * cPa);
        betA[j] = (t.w * sQa) / (t.z * cPa);
        const float4 u = loadT(tw4, k + 256, j);
        alpB[j] = (u.y * sQb) / (u.x * cPb);
        betB[j] = (u.w * sQb) / (u.z * cPb);
        const int qa = k ^ (1 << j);
        float ca = 1.f;
        for (int i = 0; i < j; ++i) ca *= loadT(tw4, qa, i).x;
        sQa = loadT(tw4, qa, j).z * ca;
        const int qb = (k + 256) ^ (1 << j);
        float cb = 1.f;
        for (int i = 0; i < j; ++i) cb *= loadT(tw4, qb, i).x;
        sQb = loadT(tw4, qb, j).z * cb;
        cPa *= t.x;  cPb *= u.x;
    }
    // stage 8 (thread-local): deferred coefs + output scales (loadT w/ rsw)
    const float4 t8a = loadT(tw4, k, 8);
    const float4 t8b = loadT(tw4, k + 256, 8);
    const float a8A = (t8a.y * sQa) / (t8a.x * cPa);
    const float b8A = (t8a.w * sQa) / (t8a.z * cPa);
    const float a8B = (t8b.y * sQb) / (t8b.x * cPb);
    const float b8B = (t8b.w * sQb) / (t8b.z * cPb);
    const float c8a = t8a.x * cPa, d8a = t8a.z * cPa;   // P8a(elem k), S8a(elem k+256)
    const float c8b = t8b.x * cPb, d8b = t8b.z * cPb;   // P8b(elem k+768), S8b(elem k+512)

    // stage 9: RAW twiddles, explicit element wiring (validated in R13/R14)
    const float4 t9a = tw4[9 * 512 + k];         // pair (k, k+512)
    const float4 t9b = tw4[9 * 512 + k + 256];   // pair (k+256, k+768)
    const float A00 = t9a.x * c8a, A01 = t9a.y * d8b;   // out[k]     from (P8a,S8b)
    const float A10 = t9a.z * c8a, A11 = t9a.w * d8b;   // out[k+512]
    const float B00 = t9b.x * d8a, B01 = t9b.y * c8b;   // out[k+256] from (S8a,P8b)
    const float B10 = t9b.z * d8a, B11 = t9b.w * c8b;   // out[k+768]
    const float bias0 = bias[k],       bias1 = bias[k + 256];
    const float bias2 = bias[k + 512], bias3 = bias[k + 768];

    const int ntrip = (nrows + 2) / 3;
    __syncthreads();                 // mbarriers initialized

    // ---- prologue: issue bulk loads for iterations 0 and 1 ----------------
    const int pi0 = blockIdx.x;
    if (k == 0) {
#pragma unroll
        for (int d = 0; d < 2; ++d) {
            const int p = pi0 + d * GRID;
            if (p < ntrip) {
                const int r0 = 3 * p;
                const int nv = (nrows - r0 >= 3) ? 3 : (nrows - r0);
                mbar_expect_tx(mb0 + 8u * d, (uint32_t)nv * 4096u);
                bulk_ld(rg0 + 12288u * d, x + (size_t)r0 * 1024,
                        (uint32_t)nv * 4096u, mb0 + 8u * d);
            }
        }
    }

    int pi = pi0;
    int slot = 0, par = 0;
    while (pi < ntrip) {
        // ---- issue bulk load for iteration i+2 -----------------------------
        if (k == 0) {
            const int p = pi + 2 * GRID;
            if (p < ntrip) {
                int s2 = slot + 2; if (s2 >= 3) s2 -= 3;
                const int r0 = 3 * p;
                const int nv = (nrows - r0 >= 3) ? 3 : (nrows - r0);
                mbar_expect_tx(mb0 + 8u * s2, (uint32_t)nv * 4096u);
                bulk_ld(rg0 + 12288u * s2, x + (size_t)r0 * 1024,
                        (uint32_t)nv * 4096u, mb0 + 8u * s2);
            }
        }

        // ---- wait for this iteration's data, read own operands -------------
        mbar_wait(mb0 + 8u * slot, par);
        const float* R = &ring[slot][0];
        const float2 va0 = *reinterpret_cast<const float2*>(&R[2 * k]);
        const float2 vb0 = *reinterpret_cast<const float2*>(&R[512 + 2 * k]);
        const float2 va1 = *reinterpret_cast<const float2*>(&R[1024 + 2 * k]);
        const float2 vb1 = *reinterpret_cast<const float2*>(&R[1536 + 2 * k]);
        const float2 va2 = *reinterpret_cast<const float2*>(&R[2048 + 2 * k]);
        const float2 vb2 = *reinterpret_cast<const float2*>(&R[2560 + 2 * k]);

        float Pa0 = va0.x, Qa0 = va0.y, Pb0 = vb0.x, Qb0 = vb0.y;
        float Pa1 = va1.x, Qa1 = va1.y, Pb1 = vb1.x, Qb1 = vb1.y;
        float Pa2 = va2.x, Qa2 = va2.y, Pb2 = vb2.x, Qb2 = vb2.y;

#pragma unroll
        for (int j = 0; j < 8; ++j) {
            const float Sa0 = fmaf(betA[j], Qa0, Pa0);
            Pa0             = fmaf(alpA[j], Qa0, Pa0);
            const float Sb0 = fmaf(betB[j], Qb0, Pb0);
            Pb0             = fmaf(alpB[j], Qb0, Pb0);
            const float Sa1 = fmaf(betA[j], Qa1, Pa1);
            Pa1             = fmaf(alpA[j], Qa1, Pa1);
            const float Sb1 = fmaf(betB[j], Qb1, Pb1);
            Pb1             = fmaf(alpB[j], Qb1, Pb1);
            const float Sa2 = fmaf(betA[j], Qa2, Pa2);
            Pa2             = fmaf(alpA[j], Qa2, Pa2);
            const float Sb2 = fmaf(betB[j], Qb2, Pb2);
            Pb2             = fmaf(alpB[j], Qb2, Pb2);

            if (j <= 4) {
                const int d = 1 << j;
                Qa0 = __shfl_xor_sync(0xffffffffu, Sa0, d);
                Qb0 = __shfl_xor_sync(0xffffffffu, Sb0, d);
                Qa1 = __shfl_xor_sync(0xffffffffu, Sa1, d);
                Qb1 = __shfl_xor_sync(0xffffffffu, Sb1, d);
                Qa2 = __shfl_xor_sync(0xffffffffu, Sa2, d);
                Qb2 = __shfl_xor_sync(0xffffffffu, Sb2, d);
            } else if (j == 5) {
                ex2A[k]       = make_float2(Sa0, Sa1);
                ex2A[256 + k] = make_float2(Sb0, Sb1);
                ex1A[k]       = Sa2;
                ex1A[256 + k] = Sb2;
                barx(1 + (w >> 1), 64);            // warp-pair {w, w^1}
                const float2 qa = ex2A[k ^ 32];
                const float2 qb = ex2A[256 + (k ^ 32)];
                Qa0 = qa.x; Qa1 = qa.y; Qb0 = qb.x; Qb1 = qb.y;
                Qa2 = ex1A[k ^ 32];  Qb2 = ex1A[256 + (k ^ 32)];
            } else if (j == 6) {
                ex2B[k]       = make_float2(Sa0, Sa1);
                ex2B[256 + k] = make_float2(Sb0, Sb1);
                ex1B[k]       = Sa2;
                ex1B[256 + k] = Sb2;
                barx(5 + (w >> 2), 128);           // warp quad
                const float2 qa = ex2B[k ^ 64];
                const float2 qb = ex2B[256 + (k ^ 64)];
                Qa0 = qa.x; Qa1 = qa.y; Qb0 = qb.x; Qb1 = qb.y;
                Qa2 = ex1B[k ^ 64];  Qb2 = ex1B[256 + (k ^ 64)];
            } else {  // j == 7
                ex2C[k]       = make_float2(Sa0, Sa1);
                ex2C[256 + k] = make_float2(Sb0, Sb1);
                ex1C[k]       = Sa2;
                ex1C[256 + k] = Sb2;
                __syncthreads();                   // 256-thread block sync
                const float2 qa = ex2C[k ^ 128];
                const float2 qb = ex2C[256 + (k ^ 128)];
                Qa0 = qa.x; Qa1 = qa.y; Qb0 = qb.x; Qb1 = qb.y;
                Qa2 = ex1C[k ^ 128]; Qb2 = ex1C[256 + (k ^ 128)];
            }
        }

        // ---- stages 8 (local, deferred) + 9 (local, folds) + bias ----------
        const int r0 = 3 * pi;
        {
            const float P8a = fmaf(a8A, Qa0, Pa0);
            const float S8a = fmaf(b8A, Qa0, Pa0);
            const float P8b = fmaf(a8B, Qb0, Pb0);
            const float S8b = fmaf(b8B, Qb0, Pb0);
            float* o = out + (size_t)r0 * 1024;
            __stcs(o + k,       fmaf(A00, P8a, fmaf(A01, S8b, bias0)));
            __stcs(o + k + 256, fmaf(B00, S8a, fmaf(B01, P8b, bias1)));
            __stcs(o + k + 512, fmaf(A10, P8a, fmaf(A11, S8b, bias2)));
            __stcs(o + k + 768, fmaf(B10, S8a, fmaf(B11, P8b, bias3)));
        }
        if (r0 + 1 < nrows) {
            const float P8a = fmaf(a8A, Qa1, Pa1);
            const float S8a = fmaf(b8A, Qa1, Pa1);
            const float P8b = fmaf(a8B, Qb1, Pb1);
            const float S8b = fmaf(b8B, Qb1, Pb1);
            float* o = out + (size_t)(r0 + 1) * 1024;
            __stcs(o + k,       fmaf(A00, P8a, fmaf(A01, S8b, bias0)));
            __stcs(o + k + 256, fmaf(B00, S8a, fmaf(B01, P8b, bias1)));
            __stcs(o + k + 512, fmaf(A10, P8a, fmaf(A11, S8b, bias2)));
            __stcs(o + k + 768, fmaf(B10, S8a, fmaf(B11, P8b, bias3)));
        }
        if (r0 + 2 < nrows) {
            const float P8a = fmaf(a8A, Qa2, Pa2);
            const float S8a = fmaf(b8A, Qa2, Pa2);
            const float P8b = fmaf(a8B, Qb2, Pb2);
            const float S8b = fmaf(b8B, Qb2, Pb2);
            float* o = out + (size_t)(r0 + 2) * 1024;
            __stcs(o + k,       fmaf(A00, P8a, fmaf(A01, S8b, bias0)));
            __stcs(o + k + 256, fmaf(B00, S8a, fmaf(B01, P8b, bias1)));
            __stcs(o + k + 512, fmaf(A10, P8a, fmaf(A11, S8b, bias2)));
            __stcs(o + k + 768, fmaf(B10, S8a, fmaf(B11, P8b, bias3)));
        }

        pi += GRID;
        ++slot;
        if (slot == 3) { slot = 0; par ^= 1; }
    }
}

extern "C" void kernel_launch(void* const* d_in, const int* in_sizes, int n_in,
                              void* d_out, int out_size)
{
    const float* x  = nullptr;
    const float* tw = nullptr;
    const float* bs = nullptr;
    long long x_elems = 0;
    for (int i = 0; i < n_in; ++i) {
        if (in_sizes[i] == 20480)     tw = (const float*)d_in[i];
        else if (in_sizes[i] == 1024) bs = (const float*)d_in[i];
        else { x = (const float*)d_in[i]; x_elems = in_sizes[i]; }
    }
    const int nrows = (int)(x_elems / 1024);

    butterfly_kernel<<<GRID, TPB>>>(x, tw, bs, (float*)d_out, nrows);
}